// round 13
// baseline (speedup 1.0000x reference)
#include <cuda_runtime.h>
#include <stdint.h>

// ---------------- problem constants ----------------
#define NVAR 4
#define BATCH 32
#define TSTEPS 256
#define KLANES 1024          // NOUT * NFEAT

struct Keys { unsigned v[20]; };

static __device__ float g_w2[NVAR * 1057 * 32];            // reordered: [0..31]=a1 ch, [32..1055]=y2 k, [1056]=bias
static __device__ float g_a1s[NVAR * BATCH * 32 * TSTEPS]; // [n][b][c][t]
static __device__ float g_beta1[NVAR * TSTEPS * KLANES];   // [n][t][k]
static __device__ float g_beta2[NVAR * TSTEPS * KLANES];

// ---------------- threefry2x32-20 (JAX-compatible), device ----------------
__device__ __forceinline__ void tf2x32(unsigned k0, unsigned k1,
                                       unsigned x0, unsigned x1,
                                       unsigned& o0, unsigned& o1) {
    unsigned ks2 = k0 ^ k1 ^ 0x1BD11BDAu;
    x0 += k0; x1 += k1;
#define TFR(r) { x0 += x1; x1 = (x1 << (r)) | (x1 >> (32 - (r))); x1 ^= x0; }
    TFR(13) TFR(15) TFR(26) TFR(6)
    x0 += k1; x1 += ks2 + 1u;
    TFR(17) TFR(29) TFR(16) TFR(24)
    x0 += ks2; x1 += k0 + 2u;
    TFR(13) TFR(15) TFR(26) TFR(6)
    x0 += k0; x1 += k1 + 3u;
    TFR(17) TFR(29) TFR(16) TFR(24)
    x0 += k1; x1 += ks2 + 4u;
    TFR(13) TFR(15) TFR(26) TFR(6)
    x0 += ks2; x1 += k0 + 5u;
#undef TFR
    o0 = x0; o1 = x1;
}

__device__ __forceinline__ float tf_uniform(unsigned k0, unsigned k1, unsigned ctr) {
    unsigned o0, o1;
    tf2x32(k0, k1, 0u, ctr, o0, o1);
    unsigned bits = o0 ^ o1;
    return __uint_as_float((bits >> 9) | 0x3f800000u) - 1.0f;
}

__device__ __forceinline__ float sigmoidf_(float x) {
    return 1.0f / (1.0f + expf(-x));
}

__device__ __forceinline__ float theta_eff(float t) {
    t = fminf(fmaxf(t, -10.0f), 10.0f);
    if (fabsf(t) < 0.01f) t = 0.0f;
    return t;
}

// ---------------- cp.async helpers ----------------
__device__ __forceinline__ void cp16(uint32_t smem_addr, const void* gptr) {
    asm volatile("cp.async.ca.shared.global [%0], [%1], 16;\n"
                 :: "r"(smem_addr), "l"(gptr));
}
__device__ __forceinline__ void cp_commit() {
    asm volatile("cp.async.commit_group;\n" ::: "memory");
}
__device__ __forceinline__ void cp_wait0() {
    asm volatile("cp.async.wait_group 0;\n" ::: "memory");
}

// ================= megakernel A: beta(both banks) | pmac1(+w1) | prep_w2 =================
// blocks [0..4095] beta (both banks per thread, 6 ILP threefry chains),
// [4096..4223] pmac1, [4224..4351] prep_w2. 256 thr.
__global__ void __launch_bounds__(256) k_A(Keys kk,
                                           const float* __restrict__ x,
                                           const float* __restrict__ theta1,
                                           const float* __restrict__ theta2,
                                           const float* __restrict__ Rlf,
                                           const float* __restrict__ Clf) {
    int blk = blockIdx.x;
    int tid = threadIdx.x;

    if (blk < 4096) {
        // -------- beta tables, both banks, layout [n][t][k] --------
        unsigned gid = (unsigned)blk * 256u + (unsigned)tid;   // 0 .. 1M-1
        int k = gid & 1023;
        int n = (gid >> 10) & 3;
        int t = gid >> 12;
        unsigned ctr = (unsigned)(((t * 1024) + k) * 4 + n);   // iota over (T,K,N,1)
        // bank 0 (6 independent threefry chains total across both banks)
        float nR0 = (tf_uniform(kk.v[4],  kk.v[5],  ctr) * 2.0f - 1.0f) * 0.05f + 1.0f;
        float nC0 = (tf_uniform(kk.v[6],  kk.v[7],  ctr) * 2.0f - 1.0f) * 0.05f + 1.0f;
        float mu0 = tf_uniform(kk.v[8],  kk.v[9],  ctr) * 0.2f + 1.0f;
        float nR1 = (tf_uniform(kk.v[12], kk.v[13], ctr) * 2.0f - 1.0f) * 0.05f + 1.0f;
        float nC1 = (tf_uniform(kk.v[14], kk.v[15], ctr) * 2.0f - 1.0f) * 0.05f + 1.0f;
        float mu1 = tf_uniform(kk.v[16], kk.v[17], ctr) * 0.2f + 1.0f;

        {
            float R_ = Rlf[k * 2 + 0];
            float C_ = Clf[k * 2 + 0];
            float Rt = sigmoidf_(R_) * (1e7f - 1e5f) + 1e5f;
            float Ct = sigmoidf_(C_) * (1e-4f - 1e-7f) + 1e-7f;
            float RC = mu0 * (Rt * nR0) * (Ct * nC0);
            g_beta1[(n * 256 + t) * 1024 + k] = RC / (RC + 0.1f);
        }
        {
            float R_ = Rlf[k * 2 + 1];
            float C_ = Clf[k * 2 + 1];
            float Rt = sigmoidf_(R_) * (1e7f - 1e5f) + 1e5f;
            float Ct = sigmoidf_(C_) * (1e-4f - 1e-7f) + 1e-7f;
            float RC = mu1 * (Rt * nR1) * (Ct * nC1);
            g_beta2[(n * 256 + t) * 1024 + k] = RC / (RC + 0.1f);
        }

    } else if (blk < 4224) {
        // -------- pmac1: block=(n,b), thread=t --------
        __shared__ float w[33 * 32];
        int blk2 = blk - 4096;
        int n = blk2 >> 5, b = blk2 & 31;
        if (tid < 32) {
            int o = tid;
            float den = 0.0f;
            for (int m = 0; m < 34; m++) {
                float th = theta_eff(theta1[m * 32 + o]);
                float u = tf_uniform(kk.v[0], kk.v[1], (unsigned)((n * 34 + m) * 32 + o));
                float noise = (u * 2.0f - 1.0f) * 0.05f + 1.0f;
                float thn = th * noise;
                den += fabsf(thn);
                if (m < 33) w[m * 32 + o] = thn;
            }
            den += 1e-10f;
            for (int m = 0; m < 33; m++) w[m * 32 + o] = w[m * 32 + o] / den;
        }
        __syncthreads();
        int t = tid;
        float z[32];
#pragma unroll
        for (int o = 0; o < 32; o++) z[o] = w[32 * 32 + o];
        const float* xp = x + ((n * 32 + b) * 32) * 256 + t;
#pragma unroll 4
        for (int m = 0; m < 32; m++) {
            float xv = xp[m * 256];
#pragma unroll
            for (int o = 0; o < 32; o++) z[o] = fmaf(xv, w[m * 32 + o], z[o]);
        }
#pragma unroll
        for (int o = 0; o < 32; o++) {
            float a = 0.05f + 0.5f * tanhf((z[o] - 0.3f) * 3.0f);
            g_a1s[(((n * 32 + b) * 32) + o) * 256 + t] = a;
        }

    } else {
        // -------- prep_w2 (reordered) --------
        __shared__ float sh[256];
        int blk3 = blk - 4224;
        int n = blk3 >> 5, o = blk3 & 31;
        unsigned nk0 = kk.v[2], nk1 = kk.v[3];
        float part = 0.0f;
        for (int m = tid; m < 1058; m += 256) {
            float th = theta_eff(theta2[m * 32 + o]);
            float u = tf_uniform(nk0, nk1, (unsigned)((n * 1058 + m) * 32 + o));
            float noise = (u * 2.0f - 1.0f) * 0.05f + 1.0f;
            part += fabsf(th * noise);
        }
        sh[tid] = part;
        __syncthreads();
        for (int s = 128; s > 0; s >>= 1) {
            if (tid < s) sh[tid] += sh[tid + s];
            __syncthreads();
        }
        float den = sh[0] + 1e-10f;
        for (int m = tid; m < 1057; m += 256) {
            float th = theta_eff(theta2[m * 32 + o]);
            float u = tf_uniform(nk0, nk1, (unsigned)((n * 1058 + m) * 32 + o));
            float noise = (u * 2.0f - 1.0f) * 0.05f + 1.0f;
            float wv = (th * noise) / den;
            int mm;
            if (m == 1056) mm = 1056;
            else {
                int c = m / 33, r = m % 33;
                mm = (r == 0) ? c : (32 + c * 32 + (r - 1));
            }
            g_w2[(n * 1057 + mm) * 32 + o] = wv;
        }
    }
}

// ================= FUSED scan + pmac2 GEMM (R7: FFMA2 + cp.async betas) =================
// block = (n,b): 128 blocks x 1024 threads. Chunk = 8 timesteps.
// smem (floats): WS[33*32] | Y[1024][12] | RED[8][32][33] | A1[8][32] | BB[2][2][8][1024]
#define SM_WS  0
#define SM_Y   1056
#define SM_RED 13344
#define SM_A1  21792
#define SM_BB  22048
#define SM_TOT 54816          // floats -> 219264 bytes

__global__ void __launch_bounds__(1024, 1) k_fused(Keys kk, float* __restrict__ out) {
    extern __shared__ float sm[];
    float* ws_s  = sm + SM_WS;    // [0..1023] a1-ch weights, [1024..1055] bias
    float* y_s   = sm + SM_Y;     // [k][12] padded
    float* red_s = sm + SM_RED;
    float* a1_s  = sm + SM_A1;
    float* bb_s  = sm + SM_BB;    // [buf][bank][tt][k]

    int n = blockIdx.x >> 5, b = blockIdx.x & 31;
    int tid  = threadIdx.x;
    int ks   = tid >> 5;          // warp id = k-slice
    int lane = tid & 31;          // = o in GEMM phase

    const float* wg = g_w2 + n * (1057 * 32);

    // ---- small weight block to smem ----
    ws_s[tid & 1023] = wg[tid & 1023];
    if (tid < 32) ws_s[1024 + tid] = wg[1056 * 32 + tid];

    // ---- register-resident W slice: W[32+ks*32+j][lane] ----
    float wreg[32];
    {
        const float* wp = wg + (32 + ks * 32) * 32 + lane;
#pragma unroll
        for (int j = 0; j < 32; j++) wreg[j] = wp[j * 32];
    }

    // ---- scan lane setup: thread = k = tid ----
    int k = tid;
    int c = ks;
    unsigned sctr = (unsigned)((k * 4 + n) * 32 + b);
    float s1 = tf_uniform(kk.v[10], kk.v[11], sctr);
    float s2 = tf_uniform(kk.v[18], kk.v[19], sctr);
    const float* xbase = g_a1s + (((n * 32 + b) * 32) + c) * 256;  // [n][b][c][t]
    const float* bet1  = g_beta1 + n * 256 * 1024;
    const float* bet2  = g_beta2 + n * 256 * 1024;

    uint32_t bb_base = (uint32_t)__cvta_generic_to_shared(bb_s);

    // ---- prefetch chunk 0 betas (64KB): 4x 16B per thread ----
    {
        int q = tid;  // quad index 0..1023 ; each bank has 2048 quads (8192 floats)
        cp16(bb_base + (0 * 16384 + 0 * 8192) * 4 + q * 16,        bet1 + 0 * 1024 + q * 4);
        cp16(bb_base + (0 * 16384 + 0 * 8192 + 4096) * 4 + q * 16, bet1 + 0 * 1024 + 4096 + q * 4);
        cp16(bb_base + (0 * 16384 + 1 * 8192) * 4 + q * 16,        bet2 + 0 * 1024 + q * 4);
        cp16(bb_base + (0 * 16384 + 1 * 8192 + 4096) * 4 + q * 16, bet2 + 0 * 1024 + 4096 + q * 4);
        cp_commit();
    }

    // ---- reduce map (tid < 256) ----
    int rt = tid >> 5, ro = tid & 31;

    cp_wait0();
    __syncthreads();

    for (int ch = 0; ch < 32; ch++) {
        int t0 = ch * 8;
        int buf = ch & 1;

        // ---- issue prefetch for chunk ch+1 (no wait) ----
        if (ch < 31) {
            int nb = buf ^ 1;
            int tn = (ch + 1) * 8;
            int q = tid;
            uint32_t dst = bb_base + nb * 16384 * 4;
            cp16(dst + q * 16,                 bet1 + tn * 1024 + q * 4);
            cp16(dst + 4096 * 4 + q * 16,      bet1 + tn * 1024 + 4096 + q * 4);
            cp16(dst + 8192 * 4 + q * 16,      bet2 + tn * 1024 + q * 4);
            cp16(dst + 12288 * 4 + q * 16,     bet2 + tn * 1024 + 4096 + q * 4);
            cp_commit();
        }

        // ===== scan 8 steps from smem betas =====
        const float* bbp = bb_s + buf * 16384;
        float yv[8];
#pragma unroll
        for (int tt = 0; tt < 8; tt++) {
            float b1 = bbp[tt * 1024 + k];
            float b2 = bbp[8192 + tt * 1024 + k];
            float xv = xbase[t0 + tt];
            if (lane == 0) a1_s[tt * 32 + c] = xv;
            float y1 = s1;
            s1 = b1 * s1 + (1.0f - b1) * xv;
            yv[tt] = s2;                        // pre-update output
            s2 = b2 * s2 + (1.0f - b2) * y1;
        }
        *(float4*)(y_s + k * 12)     = make_float4(yv[0], yv[1], yv[2], yv[3]);
        *(float4*)(y_s + k * 12 + 4) = make_float4(yv[4], yv[5], yv[6], yv[7]);
        __syncthreads();

        // ===== GEMM (packed f32x2): lane=o, 8 t, 32-k slice =====
        unsigned long long a01 = 0ull, a23 = 0ull, a45 = 0ull, a67 = 0ull;
        const float* yrow = y_s + ks * 32 * 12;
#pragma unroll
        for (int j = 0; j < 32; j++) {
            ulonglong2 u0 = *(const ulonglong2*)(yrow + j * 12);       // t0t1 | t2t3
            ulonglong2 u1 = *(const ulonglong2*)(yrow + j * 12 + 4);   // t4t5 | t6t7
            unsigned long long wp2;
            asm("mov.b64 %0, {%1, %1};" : "=l"(wp2) : "f"(wreg[j]));
            asm("fma.rn.f32x2 %0, %1, %2, %0;" : "+l"(a01) : "l"(wp2), "l"(u0.x));
            asm("fma.rn.f32x2 %0, %1, %2, %0;" : "+l"(a23) : "l"(wp2), "l"(u0.y));
            asm("fma.rn.f32x2 %0, %1, %2, %0;" : "+l"(a45) : "l"(wp2), "l"(u1.x));
            asm("fma.rn.f32x2 %0, %1, %2, %0;" : "+l"(a67) : "l"(wp2), "l"(u1.y));
        }
        {
            float v0, v1;
            asm("mov.b64 {%0, %1}, %2;" : "=f"(v0), "=f"(v1) : "l"(a01));
            red_s[(0 * 32 + ks) * 33 + lane] = v0;
            red_s[(1 * 32 + ks) * 33 + lane] = v1;
            asm("mov.b64 {%0, %1}, %2;" : "=f"(v0), "=f"(v1) : "l"(a23));
            red_s[(2 * 32 + ks) * 33 + lane] = v0;
            red_s[(3 * 32 + ks) * 33 + lane] = v1;
            asm("mov.b64 {%0, %1}, %2;" : "=f"(v0), "=f"(v1) : "l"(a45));
            red_s[(4 * 32 + ks) * 33 + lane] = v0;
            red_s[(5 * 32 + ks) * 33 + lane] = v1;
            asm("mov.b64 {%0, %1}, %2;" : "=f"(v0), "=f"(v1) : "l"(a67));
            red_s[(6 * 32 + ks) * 33 + lane] = v0;
            red_s[(7 * 32 + ks) * 33 + lane] = v1;
        }
        __syncthreads();

        // ===== reduce + a1 term + bias + act + store =====
        if (tid < 256) {
            float z0 = ws_s[1024 + ro];          // bias
            float z1 = 0.f, z2 = 0.f, z3 = 0.f;
#pragma unroll
            for (int j = 0; j < 32; j += 4) {
                z0 += red_s[(rt * 32 + j + 0) * 33 + ro];
                z1 += red_s[(rt * 32 + j + 1) * 33 + ro];
                z2 += red_s[(rt * 32 + j + 2) * 33 + ro];
                z3 += red_s[(rt * 32 + j + 3) * 33 + ro];
            }
#pragma unroll
            for (int cc = 0; cc < 32; cc += 4) {
                z0 = fmaf(ws_s[(cc + 0) * 32 + ro], a1_s[rt * 32 + cc + 0], z0);
                z1 = fmaf(ws_s[(cc + 1) * 32 + ro], a1_s[rt * 32 + cc + 1], z1);
                z2 = fmaf(ws_s[(cc + 2) * 32 + ro], a1_s[rt * 32 + cc + 2], z2);
                z3 = fmaf(ws_s[(cc + 3) * 32 + ro], a1_s[rt * 32 + cc + 3], z3);
            }
            float z = (z0 + z1) + (z2 + z3);
            float a = 0.05f + 0.5f * tanhf((z - 0.3f) * 3.0f);
            out[((n * 32 + b) * 32 + ro) * 256 + t0 + rt] = a;
        }
        cp_wait0();
        __syncthreads();
    }
}

// ---------------- host-side threefry for key derivation ----------------
static void h_tf2x32(unsigned k0, unsigned k1, unsigned x0, unsigned x1,
                     unsigned& o0, unsigned& o1) {
    unsigned ks2 = k0 ^ k1 ^ 0x1BD11BDAu;
    x0 += k0; x1 += k1;
#define HTFR(r) { x0 += x1; x1 = (x1 << (r)) | (x1 >> (32 - (r))); x1 ^= x0; }
    HTFR(13) HTFR(15) HTFR(26) HTFR(6)
    x0 += k1; x1 += ks2 + 1u;
    HTFR(17) HTFR(29) HTFR(16) HTFR(24)
    x0 += ks2; x1 += k0 + 2u;
    HTFR(13) HTFR(15) HTFR(26) HTFR(6)
    x0 += k0; x1 += k1 + 3u;
    HTFR(17) HTFR(29) HTFR(16) HTFR(24)
    x0 += k1; x1 += ks2 + 4u;
    HTFR(13) HTFR(15) HTFR(26) HTFR(6)
    x0 += ks2; x1 += k0 + 5u;
#undef HTFR
    o0 = x0; o1 = x1;
}

// ---------------- launch ----------------
extern "C" void kernel_launch(void* const* d_in, const int* in_sizes, int n_in,
                              void* d_out, int out_size) {
    (void)in_sizes; (void)n_in; (void)out_size;
    const float* x      = (const float*)d_in[0];   // (4,32,32,256)
    const float* theta1 = (const float*)d_in[1];   // (34,32)
    const float* theta2 = (const float*)d_in[2];   // (1058,32)
    const float* Rlf    = (const float*)d_in[3];   // (32,32,2)
    const float* Clf    = (const float*)d_in[4];   // (32,32,2)
    float* out = (float*)d_out;

    Keys kk;
    unsigned ck[8];
    for (int i = 0; i < 4; i++) h_tf2x32(0u, 42u, 0u, (unsigned)i, ck[2 * i], ck[2 * i + 1]);
    kk.v[0] = ck[0]; kk.v[1] = ck[1];   // k1 (pmac1 noise)
    kk.v[2] = ck[6]; kk.v[3] = ck[7];   // k4 (pmac2 noise)
    for (int bank = 0; bank < 2; bank++) {
        unsigned b0 = ck[2 + 2 * bank], b1 = ck[3 + 2 * bank];  // k2 / k3
        for (int j = 0; j < 4; j++)
            h_tf2x32(b0, b1, 0u, (unsigned)j,
                     kk.v[4 + bank * 8 + 2 * j], kk.v[4 + bank * 8 + 2 * j + 1]);
    }

    static int smem_set = 0;
    if (!smem_set) {
        cudaFuncSetAttribute(k_fused, cudaFuncAttributeMaxDynamicSharedMemorySize,
                             SM_TOT * sizeof(float));
        smem_set = 1;
    }

    k_A<<<4352, 256>>>(kk, x, theta1, theta2, Rlf, Clf);
    k_fused<<<128, 1024, SM_TOT * sizeof(float)>>>(kk, out);
}

// round 14
// speedup vs baseline: 1.5411x; 1.5411x over previous
#include <cuda_runtime.h>
#include <stdint.h>

// ---------------- problem constants ----------------
#define NVAR 4
#define BATCH 32
#define TSTEPS 256
#define KLANES 1024          // NOUT * NFEAT

struct Keys { unsigned v[20]; };

static __device__ float g_w2[NVAR * 1057 * 32];            // reordered: [0..31]=a1 ch, [32..1055]=y2 k, [1056]=bias
static __device__ float g_a1s[NVAR * BATCH * 32 * TSTEPS]; // [n][b][c][t]
static __device__ float g_beta1[NVAR * TSTEPS * KLANES];   // [n][t][k]
static __device__ float g_beta2[NVAR * TSTEPS * KLANES];

// ---------------- threefry2x32-20 (JAX-compatible), device ----------------
__device__ __forceinline__ void tf2x32(unsigned k0, unsigned k1,
                                       unsigned x0, unsigned x1,
                                       unsigned& o0, unsigned& o1) {
    unsigned ks2 = k0 ^ k1 ^ 0x1BD11BDAu;
    x0 += k0; x1 += k1;
#define TFR(r) { x0 += x1; x1 = (x1 << (r)) | (x1 >> (32 - (r))); x1 ^= x0; }
    TFR(13) TFR(15) TFR(26) TFR(6)
    x0 += k1; x1 += ks2 + 1u;
    TFR(17) TFR(29) TFR(16) TFR(24)
    x0 += ks2; x1 += k0 + 2u;
    TFR(13) TFR(15) TFR(26) TFR(6)
    x0 += k0; x1 += k1 + 3u;
    TFR(17) TFR(29) TFR(16) TFR(24)
    x0 += k1; x1 += ks2 + 4u;
    TFR(13) TFR(15) TFR(26) TFR(6)
    x0 += ks2; x1 += k0 + 5u;
#undef TFR
    o0 = x0; o1 = x1;
}

__device__ __forceinline__ float tf_uniform(unsigned k0, unsigned k1, unsigned ctr) {
    unsigned o0, o1;
    tf2x32(k0, k1, 0u, ctr, o0, o1);
    unsigned bits = o0 ^ o1;
    return __uint_as_float((bits >> 9) | 0x3f800000u) - 1.0f;
}

__device__ __forceinline__ float sigmoidf_(float x) {
    return 1.0f / (1.0f + expf(-x));
}

__device__ __forceinline__ float theta_eff(float t) {
    t = fminf(fmaxf(t, -10.0f), 10.0f);
    if (fabsf(t) < 0.01f) t = 0.0f;
    return t;
}

// ---------------- cp.async helpers ----------------
__device__ __forceinline__ void cp16(uint32_t smem_addr, const void* gptr) {
    asm volatile("cp.async.ca.shared.global [%0], [%1], 16;\n"
                 :: "r"(smem_addr), "l"(gptr));
}
__device__ __forceinline__ void cp_commit() {
    asm volatile("cp.async.commit_group;\n" ::: "memory");
}
__device__ __forceinline__ void cp_wait0() {
    asm volatile("cp.async.wait_group 0;\n" ::: "memory");
}

// ================= megakernel A: beta | pmac1(+w1) | prep_w2 =================
__global__ void __launch_bounds__(256) k_A(Keys kk,
                                           const float* __restrict__ x,
                                           const float* __restrict__ theta1,
                                           const float* __restrict__ theta2,
                                           const float* __restrict__ Rlf,
                                           const float* __restrict__ Clf) {
    int blk = blockIdx.x;
    int tid = threadIdx.x;

    if (blk < 8192) {
        // -------- beta tables, layout [n][t][k] --------
        unsigned gid = (unsigned)blk * 256u + (unsigned)tid;   // 0 .. 2M-1
        int bank = gid >> 20;
        unsigned rest = gid & 0xFFFFFu;
        int k = rest & 1023;
        int n = (rest >> 10) & 3;
        int t = rest >> 12;
        int off = 4 + bank * 8;
        unsigned ctr = (unsigned)(((t * 1024) + k) * 4 + n);   // iota over (T,K,N,1)
        float nR = (tf_uniform(kk.v[off + 0], kk.v[off + 1], ctr) * 2.0f - 1.0f) * 0.05f + 1.0f;
        float nC = (tf_uniform(kk.v[off + 2], kk.v[off + 3], ctr) * 2.0f - 1.0f) * 0.05f + 1.0f;
        float mu = tf_uniform(kk.v[off + 4], kk.v[off + 5], ctr) * 0.2f + 1.0f;
        float R_ = Rlf[k * 2 + bank];
        float C_ = Clf[k * 2 + bank];
        float Rt = sigmoidf_(R_) * (1e7f - 1e5f) + 1e5f;
        float Ct = sigmoidf_(C_) * (1e-4f - 1e-7f) + 1e-7f;
        float RC = mu * (Rt * nR) * (Ct * nC);
        float beta = RC / (RC + 0.1f);
        float* dst = bank ? g_beta2 : g_beta1;
        dst[(n * 256 + t) * 1024 + k] = beta;

    } else if (blk < 8320) {
        // -------- pmac1: block=(n,b), thread=t --------
        __shared__ float w[33 * 32];
        int blk2 = blk - 8192;
        int n = blk2 >> 5, b = blk2 & 31;
        if (tid < 32) {
            int o = tid;
            float den = 0.0f;
            for (int m = 0; m < 34; m++) {
                float th = theta_eff(theta1[m * 32 + o]);
                float u = tf_uniform(kk.v[0], kk.v[1], (unsigned)((n * 34 + m) * 32 + o));
                float noise = (u * 2.0f - 1.0f) * 0.05f + 1.0f;
                float thn = th * noise;
                den += fabsf(thn);
                if (m < 33) w[m * 32 + o] = thn;
            }
            den += 1e-10f;
            for (int m = 0; m < 33; m++) w[m * 32 + o] = w[m * 32 + o] / den;
        }
        __syncthreads();
        int t = tid;
        float z[32];
#pragma unroll
        for (int o = 0; o < 32; o++) z[o] = w[32 * 32 + o];
        const float* xp = x + ((n * 32 + b) * 32) * 256 + t;
#pragma unroll 4
        for (int m = 0; m < 32; m++) {
            float xv = xp[m * 256];
#pragma unroll
            for (int o = 0; o < 32; o++) z[o] = fmaf(xv, w[m * 32 + o], z[o]);
        }
#pragma unroll
        for (int o = 0; o < 32; o++) {
            float a = 0.05f + 0.5f * tanhf((z[o] - 0.3f) * 3.0f);
            g_a1s[(((n * 32 + b) * 32) + o) * 256 + t] = a;
        }

    } else {
        // -------- prep_w2 (reordered) --------
        __shared__ float sh[256];
        int blk3 = blk - 8320;
        int n = blk3 >> 5, o = blk3 & 31;
        unsigned nk0 = kk.v[2], nk1 = kk.v[3];
        float part = 0.0f;
        for (int m = tid; m < 1058; m += 256) {
            float th = theta_eff(theta2[m * 32 + o]);
            float u = tf_uniform(nk0, nk1, (unsigned)((n * 1058 + m) * 32 + o));
            float noise = (u * 2.0f - 1.0f) * 0.05f + 1.0f;
            part += fabsf(th * noise);
        }
        sh[tid] = part;
        __syncthreads();
        for (int s = 128; s > 0; s >>= 1) {
            if (tid < s) sh[tid] += sh[tid + s];
            __syncthreads();
        }
        float den = sh[0] + 1e-10f;
        for (int m = tid; m < 1057; m += 256) {
            float th = theta_eff(theta2[m * 32 + o]);
            float u = tf_uniform(nk0, nk1, (unsigned)((n * 1058 + m) * 32 + o));
            float noise = (u * 2.0f - 1.0f) * 0.05f + 1.0f;
            float wv = (th * noise) / den;
            int mm;
            if (m == 1056) mm = 1056;
            else {
                int c = m / 33, r = m % 33;
                mm = (r == 0) ? c : (32 + c * 32 + (r - 1));
            }
            g_w2[(n * 1057 + mm) * 32 + o] = wv;
        }
    }
}

// ================= FUSED scan + pmac2 GEMM (FFMA2 + cp.async betas) =================
// block = (n,b): 128 blocks x 1024 threads. Chunk = 8 timesteps.
// smem (floats): WS[33*32] | Y[1024][12] | RED[8][32][33] | A1[8][32] | BB[2][2][8][1024]
#define SM_WS  0
#define SM_Y   1056
#define SM_RED 13344
#define SM_A1  21792
#define SM_BB  22048
#define SM_TOT 54816          // floats -> 219264 bytes

__global__ void __launch_bounds__(1024, 1) k_fused(Keys kk, float* __restrict__ out) {
    extern __shared__ float sm[];
    float* ws_s  = sm + SM_WS;    // [0..1023] a1-ch weights, [1024..1055] = bias
    float* y_s   = sm + SM_Y;     // [k][12] padded
    float* red_s = sm + SM_RED;
    float* a1_s  = sm + SM_A1;
    float* bb_s  = sm + SM_BB;    // [buf][bank][tt][k]

    int n = blockIdx.x >> 5, b = blockIdx.x & 31;
    int tid  = threadIdx.x;
    int ks   = tid >> 5;          // warp id = k-slice
    int lane = tid & 31;          // = o in GEMM phase

    const float* wg = g_w2 + n * (1057 * 32);

    // ---- small weight block to smem ----
    ws_s[tid & 1023] = wg[tid & 1023];                      // rows 0..31
    if (tid < 32) ws_s[1024 + tid] = wg[1056 * 32 + tid];   // bias row

    // ---- register-resident W slice: W[32+ks*32+j][lane] ----
    float wreg[32];
    {
        const float* wp = wg + (32 + ks * 32) * 32 + lane;
#pragma unroll
        for (int j = 0; j < 32; j++) wreg[j] = wp[j * 32];
    }

    // ---- scan lane setup: thread = k = tid ----
    int k = tid;
    int c = ks;
    unsigned sctr = (unsigned)((k * 4 + n) * 32 + b);
    float s1 = tf_uniform(kk.v[10], kk.v[11], sctr);
    float s2 = tf_uniform(kk.v[18], kk.v[19], sctr);
    const float* xbase = g_a1s + (((n * 32 + b) * 32) + c) * 256;  // [n][b][c][t]
    const float* bet1  = g_beta1 + n * 256 * 1024;
    const float* bet2  = g_beta2 + n * 256 * 1024;

    uint32_t bb_base = (uint32_t)__cvta_generic_to_shared(bb_s);

    // ---- prefetch chunk 0 betas (64KB): 4x 16B per thread ----
    {
        int q = tid;  // quad index 0..1023 ; each bank has 2048 quads (8192 floats)
        cp16(bb_base + (0 * 16384 + 0 * 8192) * 4 + q * 16,        bet1 + 0 * 1024 + q * 4);
        cp16(bb_base + (0 * 16384 + 0 * 8192 + 4096) * 4 + q * 16, bet1 + 0 * 1024 + 4096 + q * 4);
        cp16(bb_base + (0 * 16384 + 1 * 8192) * 4 + q * 16,        bet2 + 0 * 1024 + q * 4);
        cp16(bb_base + (0 * 16384 + 1 * 8192 + 4096) * 4 + q * 16, bet2 + 0 * 1024 + 4096 + q * 4);
        cp_commit();
    }

    // ---- reduce map (tid < 256) ----
    int rt = tid >> 5, ro = tid & 31;

    cp_wait0();
    __syncthreads();

    for (int ch = 0; ch < 32; ch++) {
        int t0 = ch * 8;
        int buf = ch & 1;

        // ---- issue prefetch for chunk ch+1 (no wait) ----
        if (ch < 31) {
            int nb = buf ^ 1;
            int tn = (ch + 1) * 8;
            int q = tid;
            uint32_t dst = bb_base + nb * 16384 * 4;
            cp16(dst + q * 16,                 bet1 + tn * 1024 + q * 4);
            cp16(dst + 4096 * 4 + q * 16,      bet1 + tn * 1024 + 4096 + q * 4);
            cp16(dst + 8192 * 4 + q * 16,      bet2 + tn * 1024 + q * 4);
            cp16(dst + 12288 * 4 + q * 16,     bet2 + tn * 1024 + 4096 + q * 4);
            cp_commit();
        }

        // ===== scan 8 steps from smem betas =====
        const float* bbp = bb_s + buf * 16384;
        float yv[8];
#pragma unroll
        for (int tt = 0; tt < 8; tt++) {
            float b1 = bbp[tt * 1024 + k];
            float b2 = bbp[8192 + tt * 1024 + k];
            float xv = xbase[t0 + tt];
            if (lane == 0) a1_s[tt * 32 + c] = xv;
            float y1 = s1;
            s1 = b1 * s1 + (1.0f - b1) * xv;
            yv[tt] = s2;                        // pre-update output
            s2 = b2 * s2 + (1.0f - b2) * y1;
        }
        *(float4*)(y_s + k * 12)     = make_float4(yv[0], yv[1], yv[2], yv[3]);
        *(float4*)(y_s + k * 12 + 4) = make_float4(yv[4], yv[5], yv[6], yv[7]);
        __syncthreads();

        // ===== GEMM (packed f32x2): lane=o, 8 t, 32-k slice =====
        unsigned long long a01 = 0ull, a23 = 0ull, a45 = 0ull, a67 = 0ull;
        const float* yrow = y_s + ks * 32 * 12;
#pragma unroll
        for (int j = 0; j < 32; j++) {
            ulonglong2 u0 = *(const ulonglong2*)(yrow + j * 12);       // t0t1 | t2t3
            ulonglong2 u1 = *(const ulonglong2*)(yrow + j * 12 + 4);   // t4t5 | t6t7
            unsigned long long wp2;
            asm("mov.b64 %0, {%1, %1};" : "=l"(wp2) : "f"(wreg[j]));
            asm("fma.rn.f32x2 %0, %1, %2, %0;" : "+l"(a01) : "l"(wp2), "l"(u0.x));
            asm("fma.rn.f32x2 %0, %1, %2, %0;" : "+l"(a23) : "l"(wp2), "l"(u0.y));
            asm("fma.rn.f32x2 %0, %1, %2, %0;" : "+l"(a45) : "l"(wp2), "l"(u1.x));
            asm("fma.rn.f32x2 %0, %1, %2, %0;" : "+l"(a67) : "l"(wp2), "l"(u1.y));
        }
        {
            float v0, v1;
            asm("mov.b64 {%0, %1}, %2;" : "=f"(v0), "=f"(v1) : "l"(a01));
            red_s[(0 * 32 + ks) * 33 + lane] = v0;
            red_s[(1 * 32 + ks) * 33 + lane] = v1;
            asm("mov.b64 {%0, %1}, %2;" : "=f"(v0), "=f"(v1) : "l"(a23));
            red_s[(2 * 32 + ks) * 33 + lane] = v0;
            red_s[(3 * 32 + ks) * 33 + lane] = v1;
            asm("mov.b64 {%0, %1}, %2;" : "=f"(v0), "=f"(v1) : "l"(a45));
            red_s[(4 * 32 + ks) * 33 + lane] = v0;
            red_s[(5 * 32 + ks) * 33 + lane] = v1;
            asm("mov.b64 {%0, %1}, %2;" : "=f"(v0), "=f"(v1) : "l"(a67));
            red_s[(6 * 32 + ks) * 33 + lane] = v0;
            red_s[(7 * 32 + ks) * 33 + lane] = v1;
        }
        __syncthreads();

        // ===== reduce + a1 term + bias + act + store =====
        if (tid < 256) {
            float z0 = ws_s[1024 + ro];          // bias
            float z1 = 0.f, z2 = 0.f, z3 = 0.f;
#pragma unroll
            for (int j = 0; j < 32; j += 4) {
                z0 += red_s[(rt * 32 + j + 0) * 33 + ro];
                z1 += red_s[(rt * 32 + j + 1) * 33 + ro];
                z2 += red_s[(rt * 32 + j + 2) * 33 + ro];
                z3 += red_s[(rt * 32 + j + 3) * 33 + ro];
            }
#pragma unroll
            for (int cc = 0; cc < 32; cc += 4) {
                z0 = fmaf(ws_s[(cc + 0) * 32 + ro], a1_s[rt * 32 + cc + 0], z0);
                z1 = fmaf(ws_s[(cc + 1) * 32 + ro], a1_s[rt * 32 + cc + 1], z1);
                z2 = fmaf(ws_s[(cc + 2) * 32 + ro], a1_s[rt * 32 + cc + 2], z2);
                z3 = fmaf(ws_s[(cc + 3) * 32 + ro], a1_s[rt * 32 + cc + 3], z3);
            }
            float z = (z0 + z1) + (z2 + z3);
            float a = 0.05f + 0.5f * tanhf((z - 0.3f) * 3.0f);
            out[((n * 32 + b) * 32 + ro) * 256 + t0 + rt] = a;
        }
        cp_wait0();
        __syncthreads();
    }
}

// ---------------- host-side threefry for key derivation ----------------
static void h_tf2x32(unsigned k0, unsigned k1, unsigned x0, unsigned x1,
                     unsigned& o0, unsigned& o1) {
    unsigned ks2 = k0 ^ k1 ^ 0x1BD11BDAu;
    x0 += k0; x1 += k1;
#define HTFR(r) { x0 += x1; x1 = (x1 << (r)) | (x1 >> (32 - (r))); x1 ^= x0; }
    HTFR(13) HTFR(15) HTFR(26) HTFR(6)
    x0 += k1; x1 += ks2 + 1u;
    HTFR(17) HTFR(29) HTFR(16) HTFR(24)
    x0 += ks2; x1 += k0 + 2u;
    HTFR(13) HTFR(15) HTFR(26) HTFR(6)
    x0 += k0; x1 += k1 + 3u;
    HTFR(17) HTFR(29) HTFR(16) HTFR(24)
    x0 += k1; x1 += ks2 + 4u;
    HTFR(13) HTFR(15) HTFR(26) HTFR(6)
    x0 += ks2; x1 += k0 + 5u;
#undef HTFR
    o0 = x0; o1 = x1;
}

// ---------------- launch ----------------
extern "C" void kernel_launch(void* const* d_in, const int* in_sizes, int n_in,
                              void* d_out, int out_size) {
    (void)in_sizes; (void)n_in; (void)out_size;
    const float* x      = (const float*)d_in[0];   // (4,32,32,256)
    const float* theta1 = (const float*)d_in[1];   // (34,32)
    const float* theta2 = (const float*)d_in[2];   // (1058,32)
    const float* Rlf    = (const float*)d_in[3];   // (32,32,2)
    const float* Clf    = (const float*)d_in[4];   // (32,32,2)
    float* out = (float*)d_out;

    Keys kk;
    unsigned ck[8];
    for (int i = 0; i < 4; i++) h_tf2x32(0u, 42u, 0u, (unsigned)i, ck[2 * i], ck[2 * i + 1]);
    kk.v[0] = ck[0]; kk.v[1] = ck[1];   // k1 (pmac1 noise)
    kk.v[2] = ck[6]; kk.v[3] = ck[7];   // k4 (pmac2 noise)
    for (int bank = 0; bank < 2; bank++) {
        unsigned b0 = ck[2 + 2 * bank], b1 = ck[3 + 2 * bank];  // k2 / k3
        for (int j = 0; j < 4; j++)
            h_tf2x32(b0, b1, 0u, (unsigned)j,
                     kk.v[4 + bank * 8 + 2 * j], kk.v[4 + bank * 8 + 2 * j + 1]);
    }

    static int smem_set = 0;
    if (!smem_set) {
        cudaFuncSetAttribute(k_fused, cudaFuncAttributeMaxDynamicSharedMemorySize,
                             SM_TOT * sizeof(float));
        smem_set = 1;
    }

    k_A<<<8448, 256>>>(kk, x, theta1, theta2, Rlf, Clf);
    k_fused<<<128, 1024, SM_TOT * sizeof(float)>>>(kk, out);
}

// round 16
// speedup vs baseline: 1.6142x; 1.0474x over previous
#include <cuda_runtime.h>
#include <stdint.h>

// ---------------- problem constants ----------------
#define NVAR 4
#define BATCH 32
#define TSTEPS 256
#define KLANES 1024          // NOUT * NFEAT

struct Keys { unsigned v[20]; };

static __device__ float g_w2[NVAR * 1057 * 32];            // reordered: [0..31]=a1 ch, [32..1055]=y2 k, [1056]=bias
static __device__ float g_a1s[NVAR * BATCH * 32 * TSTEPS]; // [n][b][c][t]
static __device__ float g_beta1[NVAR * TSTEPS * KLANES];   // [n][t][k]
static __device__ float g_beta2[NVAR * TSTEPS * KLANES];

// ---------------- threefry2x32-20 (JAX-compatible), device ----------------
__device__ __forceinline__ void tf2x32(unsigned k0, unsigned k1,
                                       unsigned x0, unsigned x1,
                                       unsigned& o0, unsigned& o1) {
    unsigned ks2 = k0 ^ k1 ^ 0x1BD11BDAu;
    x0 += k0; x1 += k1;
#define TFR(r) { x0 += x1; x1 = (x1 << (r)) | (x1 >> (32 - (r))); x1 ^= x0; }
    TFR(13) TFR(15) TFR(26) TFR(6)
    x0 += k1; x1 += ks2 + 1u;
    TFR(17) TFR(29) TFR(16) TFR(24)
    x0 += ks2; x1 += k0 + 2u;
    TFR(13) TFR(15) TFR(26) TFR(6)
    x0 += k0; x1 += k1 + 3u;
    TFR(17) TFR(29) TFR(16) TFR(24)
    x0 += k1; x1 += ks2 + 4u;
    TFR(13) TFR(15) TFR(26) TFR(6)
    x0 += ks2; x1 += k0 + 5u;
#undef TFR
    o0 = x0; o1 = x1;
}

__device__ __forceinline__ float tf_uniform(unsigned k0, unsigned k1, unsigned ctr) {
    unsigned o0, o1;
    tf2x32(k0, k1, 0u, ctr, o0, o1);
    unsigned bits = o0 ^ o1;
    return __uint_as_float((bits >> 9) | 0x3f800000u) - 1.0f;
}

__device__ __forceinline__ float sigmoidf_(float x) {
    return 1.0f / (1.0f + expf(-x));
}

__device__ __forceinline__ float theta_eff(float t) {
    t = fminf(fmaxf(t, -10.0f), 10.0f);
    if (fabsf(t) < 0.01f) t = 0.0f;
    return t;
}

// ---------------- cp.async helpers ----------------
__device__ __forceinline__ void cp16(uint32_t smem_addr, const void* gptr) {
    asm volatile("cp.async.ca.shared.global [%0], [%1], 16;\n"
                 :: "r"(smem_addr), "l"(gptr));
}
__device__ __forceinline__ void cp_commit() {
    asm volatile("cp.async.commit_group;\n" ::: "memory");
}
__device__ __forceinline__ void cp_wait0() {
    asm volatile("cp.async.wait_group 0;\n" ::: "memory");
}

// ================= megakernel A: pmac1 | prep_w2 FIRST, then beta =================
// blocks [0..127] pmac1, [128..255] prep_w2 (heavy, start in wave 0),
// [256..8447] beta (short, fill remaining waves). 256 thr.
__global__ void __launch_bounds__(256) k_A(Keys kk,
                                           const float* __restrict__ x,
                                           const float* __restrict__ theta1,
                                           const float* __restrict__ theta2,
                                           const float* __restrict__ Rlf,
                                           const float* __restrict__ Clf) {
    int blk = blockIdx.x;
    int tid = threadIdx.x;

    if (blk >= 256) {
        // -------- beta tables, layout [n][t][k] --------
        unsigned gid = (unsigned)(blk - 256) * 256u + (unsigned)tid;   // 0 .. 2M-1
        int bank = gid >> 20;
        unsigned rest = gid & 0xFFFFFu;
        int k = rest & 1023;
        int n = (rest >> 10) & 3;
        int t = rest >> 12;
        int off = 4 + bank * 8;
        unsigned ctr = (unsigned)(((t * 1024) + k) * 4 + n);   // iota over (T,K,N,1)
        float nR = (tf_uniform(kk.v[off + 0], kk.v[off + 1], ctr) * 2.0f - 1.0f) * 0.05f + 1.0f;
        float nC = (tf_uniform(kk.v[off + 2], kk.v[off + 3], ctr) * 2.0f - 1.0f) * 0.05f + 1.0f;
        float mu = tf_uniform(kk.v[off + 4], kk.v[off + 5], ctr) * 0.2f + 1.0f;
        float R_ = Rlf[k * 2 + bank];
        float C_ = Clf[k * 2 + bank];
        float Rt = sigmoidf_(R_) * (1e7f - 1e5f) + 1e5f;
        float Ct = sigmoidf_(C_) * (1e-4f - 1e-7f) + 1e-7f;
        float RC = mu * (Rt * nR) * (Ct * nC);
        float beta = RC / (RC + 0.1f);
        float* dst = bank ? g_beta2 : g_beta1;
        dst[(n * 256 + t) * 1024 + k] = beta;

    } else if (blk < 128) {
        // -------- pmac1: block=(n,b), thread=t --------
        __shared__ float w[33 * 32];
        int n = blk >> 5, b = blk & 31;
        if (tid < 32) {
            int o = tid;
            float den = 0.0f;
            for (int m = 0; m < 34; m++) {
                float th = theta_eff(theta1[m * 32 + o]);
                float u = tf_uniform(kk.v[0], kk.v[1], (unsigned)((n * 34 + m) * 32 + o));
                float noise = (u * 2.0f - 1.0f) * 0.05f + 1.0f;
                float thn = th * noise;
                den += fabsf(thn);
                if (m < 33) w[m * 32 + o] = thn;
            }
            den += 1e-10f;
            for (int m = 0; m < 33; m++) w[m * 32 + o] = w[m * 32 + o] / den;
        }
        __syncthreads();
        int t = tid;
        float z[32];
#pragma unroll
        for (int o = 0; o < 32; o++) z[o] = w[32 * 32 + o];
        const float* xp = x + ((n * 32 + b) * 32) * 256 + t;
#pragma unroll 4
        for (int m = 0; m < 32; m++) {
            float xv = xp[m * 256];
#pragma unroll
            for (int o = 0; o < 32; o++) z[o] = fmaf(xv, w[m * 32 + o], z[o]);
        }
#pragma unroll
        for (int o = 0; o < 32; o++) {
            float a = 0.05f + 0.5f * tanhf((z[o] - 0.3f) * 3.0f);
            g_a1s[(((n * 32 + b) * 32) + o) * 256 + t] = a;
        }

    } else {
        // -------- prep_w2 (reordered): blocks 128..255 --------
        __shared__ float sh[256];
        int blk3 = blk - 128;
        int n = blk3 >> 5, o = blk3 & 31;
        unsigned nk0 = kk.v[2], nk1 = kk.v[3];
        float part = 0.0f;
        for (int m = tid; m < 1058; m += 256) {
            float th = theta_eff(theta2[m * 32 + o]);
            float u = tf_uniform(nk0, nk1, (unsigned)((n * 1058 + m) * 32 + o));
            float noise = (u * 2.0f - 1.0f) * 0.05f + 1.0f;
            part += fabsf(th * noise);
        }
        sh[tid] = part;
        __syncthreads();
        for (int s = 128; s > 0; s >>= 1) {
            if (tid < s) sh[tid] += sh[tid + s];
            __syncthreads();
        }
        float den = sh[0] + 1e-10f;
        for (int m = tid; m < 1057; m += 256) {
            float th = theta_eff(theta2[m * 32 + o]);
            float u = tf_uniform(nk0, nk1, (unsigned)((n * 1058 + m) * 32 + o));
            float noise = (u * 2.0f - 1.0f) * 0.05f + 1.0f;
            float wv = (th * noise) / den;
            int mm;
            if (m == 1056) mm = 1056;
            else {
                int c = m / 33, r = m % 33;
                mm = (r == 0) ? c : (32 + c * 32 + (r - 1));
            }
            g_w2[(n * 1057 + mm) * 32 + o] = wv;
        }
    }
}

// ================= FUSED scan + pmac2 GEMM (R7: FFMA2 + cp.async betas) =================
// block = (n,b): 128 blocks x 1024 threads. Chunk = 8 timesteps.
// smem (floats): WS[33*32] | Y[1024][12] | RED[8][32][33] | A1[8][32] | BB[2][2][8][1024]
#define SM_WS  0
#define SM_Y   1056
#define SM_RED 13344
#define SM_A1  21792
#define SM_BB  22048
#define SM_TOT 54816          // floats -> 219264 bytes

__global__ void __launch_bounds__(1024, 1) k_fused(Keys kk, float* __restrict__ out) {
    extern __shared__ float sm[];
    float* ws_s  = sm + SM_WS;    // [0..1023] a1-ch weights, [1024..1055] = bias
    float* y_s   = sm + SM_Y;     // [k][12] padded
    float* red_s = sm + SM_RED;
    float* a1_s  = sm + SM_A1;
    float* bb_s  = sm + SM_BB;    // [buf][bank][tt][k]

    int n = blockIdx.x >> 5, b = blockIdx.x & 31;
    int tid  = threadIdx.x;
    int ks   = tid >> 5;          // warp id = k-slice
    int lane = tid & 31;          // = o in GEMM phase

    const float* wg = g_w2 + n * (1057 * 32);

    // ---- small weight block to smem ----
    ws_s[tid & 1023] = wg[tid & 1023];                      // rows 0..31
    if (tid < 32) ws_s[1024 + tid] = wg[1056 * 32 + tid];   // bias row

    // ---- register-resident W slice: W[32+ks*32+j][lane] ----
    float wreg[32];
    {
        const float* wp = wg + (32 + ks * 32) * 32 + lane;
#pragma unroll
        for (int j = 0; j < 32; j++) wreg[j] = wp[j * 32];
    }

    // ---- scan lane setup: thread = k = tid ----
    int k = tid;
    int c = ks;
    unsigned sctr = (unsigned)((k * 4 + n) * 32 + b);
    float s1 = tf_uniform(kk.v[10], kk.v[11], sctr);
    float s2 = tf_uniform(kk.v[18], kk.v[19], sctr);
    const float* xbase = g_a1s + (((n * 32 + b) * 32) + c) * 256;  // [n][b][c][t]
    const float* bet1  = g_beta1 + n * 256 * 1024;
    const float* bet2  = g_beta2 + n * 256 * 1024;

    uint32_t bb_base = (uint32_t)__cvta_generic_to_shared(bb_s);

    // ---- prefetch chunk 0 betas (64KB): 4x 16B per thread ----
    {
        int q = tid;  // quad index 0..1023 ; each bank has 2048 quads (8192 floats)
        cp16(bb_base + (0 * 16384 + 0 * 8192) * 4 + q * 16,        bet1 + 0 * 1024 + q * 4);
        cp16(bb_base + (0 * 16384 + 0 * 8192 + 4096) * 4 + q * 16, bet1 + 0 * 1024 + 4096 + q * 4);
        cp16(bb_base + (0 * 16384 + 1 * 8192) * 4 + q * 16,        bet2 + 0 * 1024 + q * 4);
        cp16(bb_base + (0 * 16384 + 1 * 8192 + 4096) * 4 + q * 16, bet2 + 0 * 1024 + 4096 + q * 4);
        cp_commit();
    }

    // ---- reduce map (tid < 256) ----
    int rt = tid >> 5, ro = tid & 31;

    cp_wait0();
    __syncthreads();

    for (int ch = 0; ch < 32; ch++) {
        int t0 = ch * 8;
        int buf = ch & 1;

        // ---- issue prefetch for chunk ch+1 (no wait) ----
        if (ch < 31) {
            int nb = buf ^ 1;
            int tn = (ch + 1) * 8;
            int q = tid;
            uint32_t dst = bb_base + nb * 16384 * 4;
            cp16(dst + q * 16,                 bet1 + tn * 1024 + q * 4);
            cp16(dst + 4096 * 4 + q * 16,      bet1 + tn * 1024 + 4096 + q * 4);
            cp16(dst + 8192 * 4 + q * 16,      bet2 + tn * 1024 + q * 4);
            cp16(dst + 12288 * 4 + q * 16,     bet2 + tn * 1024 + 4096 + q * 4);
            cp_commit();
        }

        // ===== scan 8 steps from smem betas =====
        const float* bbp = bb_s + buf * 16384;
        float yv[8];
#pragma unroll
        for (int tt = 0; tt < 8; tt++) {
            float b1 = bbp[tt * 1024 + k];
            float b2 = bbp[8192 + tt * 1024 + k];
            float xv = xbase[t0 + tt];
            if (lane == 0) a1_s[tt * 32 + c] = xv;
            float y1 = s1;
            s1 = b1 * s1 + (1.0f - b1) * xv;
            yv[tt] = s2;                        // pre-update output
            s2 = b2 * s2 + (1.0f - b2) * y1;
        }
        *(float4*)(y_s + k * 12)     = make_float4(yv[0], yv[1], yv[2], yv[3]);
        *(float4*)(y_s + k * 12 + 4) = make_float4(yv[4], yv[5], yv[6], yv[7]);
        __syncthreads();

        // ===== GEMM (packed f32x2): lane=o, 8 t, 32-k slice =====
        unsigned long long a01 = 0ull, a23 = 0ull, a45 = 0ull, a67 = 0ull;
        const float* yrow = y_s + ks * 32 * 12;
#pragma unroll
        for (int j = 0; j < 32; j++) {
            ulonglong2 u0 = *(const ulonglong2*)(yrow + j * 12);       // t0t1 | t2t3
            ulonglong2 u1 = *(const ulonglong2*)(yrow + j * 12 + 4);   // t4t5 | t6t7
            unsigned long long wp2;
            asm("mov.b64 %0, {%1, %1};" : "=l"(wp2) : "f"(wreg[j]));
            asm("fma.rn.f32x2 %0, %1, %2, %0;" : "+l"(a01) : "l"(wp2), "l"(u0.x));
            asm("fma.rn.f32x2 %0, %1, %2, %0;" : "+l"(a23) : "l"(wp2), "l"(u0.y));
            asm("fma.rn.f32x2 %0, %1, %2, %0;" : "+l"(a45) : "l"(wp2), "l"(u1.x));
            asm("fma.rn.f32x2 %0, %1, %2, %0;" : "+l"(a67) : "l"(wp2), "l"(u1.y));
        }
        {
            float v0, v1;
            asm("mov.b64 {%0, %1}, %2;" : "=f"(v0), "=f"(v1) : "l"(a01));
            red_s[(0 * 32 + ks) * 33 + lane] = v0;
            red_s[(1 * 32 + ks) * 33 + lane] = v1;
            asm("mov.b64 {%0, %1}, %2;" : "=f"(v0), "=f"(v1) : "l"(a23));
            red_s[(2 * 32 + ks) * 33 + lane] = v0;
            red_s[(3 * 32 + ks) * 33 + lane] = v1;
            asm("mov.b64 {%0, %1}, %2;" : "=f"(v0), "=f"(v1) : "l"(a45));
            red_s[(4 * 32 + ks) * 33 + lane] = v0;
            red_s[(5 * 32 + ks) * 33 + lane] = v1;
            asm("mov.b64 {%0, %1}, %2;" : "=f"(v0), "=f"(v1) : "l"(a67));
            red_s[(6 * 32 + ks) * 33 + lane] = v0;
            red_s[(7 * 32 + ks) * 33 + lane] = v1;
        }
        __syncthreads();

        // ===== reduce + a1 term + bias + act + store =====
        if (tid < 256) {
            float z0 = ws_s[1024 + ro];          // bias
            float z1 = 0.f, z2 = 0.f, z3 = 0.f;
#pragma unroll
            for (int j = 0; j < 32; j += 4) {
                z0 += red_s[(rt * 32 + j + 0) * 33 + ro];
                z1 += red_s[(rt * 32 + j + 1) * 33 + ro];
                z2 += red_s[(rt * 32 + j + 2) * 33 + ro];
                z3 += red_s[(rt * 32 + j + 3) * 33 + ro];
            }
#pragma unroll
            for (int cc = 0; cc < 32; cc += 4) {
                z0 = fmaf(ws_s[(cc + 0) * 32 + ro], a1_s[rt * 32 + cc + 0], z0);
                z1 = fmaf(ws_s[(cc + 1) * 32 + ro], a1_s[rt * 32 + cc + 1], z1);
                z2 = fmaf(ws_s[(cc + 2) * 32 + ro], a1_s[rt * 32 + cc + 2], z2);
                z3 = fmaf(ws_s[(cc + 3) * 32 + ro], a1_s[rt * 32 + cc + 3], z3);
            }
            float z = (z0 + z1) + (z2 + z3);
            float a = 0.05f + 0.5f * tanhf((z - 0.3f) * 3.0f);
            out[((n * 32 + b) * 32 + ro) * 256 + t0 + rt] = a;
        }
        cp_wait0();
        __syncthreads();
    }
}

// ---------------- host-side threefry for key derivation ----------------
static void h_tf2x32(unsigned k0, unsigned k1, unsigned x0, unsigned x1,
                     unsigned& o0, unsigned& o1) {
    unsigned ks2 = k0 ^ k1 ^ 0x1BD11BDAu;
    x0 += k0; x1 += k1;
#define HTFR(r) { x0 += x1; x1 = (x1 << (r)) | (x1 >> (32 - (r))); x1 ^= x0; }
    HTFR(13) HTFR(15) HTFR(26) HTFR(6)
    x0 += k1; x1 += ks2 + 1u;
    HTFR(17) HTFR(29) HTFR(16) HTFR(24)
    x0 += ks2; x1 += k0 + 2u;
    HTFR(13) HTFR(15) HTFR(26) HTFR(6)
    x0 += k0; x1 += k1 + 3u;
    HTFR(17) HTFR(29) HTFR(16) HTFR(24)
    x0 += k1; x1 += ks2 + 4u;
    HTFR(13) HTFR(15) HTFR(26) HTFR(6)
    x0 += ks2; x1 += k0 + 5u;
#undef HTFR
    o0 = x0; o1 = x1;
}

// ---------------- launch ----------------
extern "C" void kernel_launch(void* const* d_in, const int* in_sizes, int n_in,
                              void* d_out, int out_size) {
    (void)in_sizes; (void)n_in; (void)out_size;
    const float* x      = (const float*)d_in[0];   // (4,32,32,256)
    const float* theta1 = (const float*)d_in[1];   // (34,32)
    const float* theta2 = (const float*)d_in[2];   // (1058,32)
    const float* Rlf    = (const float*)d_in[3];   // (32,32,2)
    const float* Clf    = (const float*)d_in[4];   // (32,32,2)
    float* out = (float*)d_out;

    Keys kk;
    unsigned ck[8];
    for (int i = 0; i < 4; i++) h_tf2x32(0u, 42u, 0u, (unsigned)i, ck[2 * i], ck[2 * i + 1]);
    kk.v[0] = ck[0]; kk.v[1] = ck[1];   // k1 (pmac1 noise)
    kk.v[2] = ck[6]; kk.v[3] = ck[7];   // k4 (pmac2 noise)
    for (int bank = 0; bank < 2; bank++) {
        unsigned b0 = ck[2 + 2 * bank], b1 = ck[3 + 2 * bank];  // k2 / k3
        for (int j = 0; j < 4; j++)
            h_tf2x32(b0, b1, 0u, (unsigned)j,
                     kk.v[4 + bank * 8 + 2 * j], kk.v[4 + bank * 8 + 2 * j + 1]);
    }

    static int smem_set = 0;
    if (!smem_set) {
        cudaFuncSetAttribute(k_fused, cudaFuncAttributeMaxDynamicSharedMemorySize,
                             SM_TOT * sizeof(float));
        smem_set = 1;
    }

    k_A<<<8448, 256>>>(kk, x, theta1, theta2, Rlf, Clf);
    k_fused<<<128, 1024, SM_TOT * sizeof(float)>>>(kk, out);
}